// round 15
// baseline (speedup 1.0000x reference)
#include <cuda_runtime.h>
#include <cuda_fp16.h>
#include <cstdint>

// Problem constants
#define B_   2
#define L_   2048
#define Q_   4096
#define D_   512
#define H_   8
#define HD_  64

// ---------------------------------------------------------------------------
// Scratch (allocation-free __device__ globals), all fp16.
// ---------------------------------------------------------------------------
__device__ __half g_x [B_ * L_ * D_];
__device__ __half g_wq[D_ * D_];
__device__ __half g_wk[D_ * D_];
__device__ __half g_wv[D_ * D_];
__device__ __half g_wo[D_ * D_];
__device__ __half g_xq[B_ * L_ * D_];
__device__ __half g_k [B_ * L_ * D_];
__device__ __half g_v [B_ * L_ * D_];
__device__ __half g_ao[B_ * Q_ * D_];

// ---------------------------------------------------------------------------
// Helpers
// ---------------------------------------------------------------------------
__device__ __forceinline__ uint32_t packh2(float a, float b) {
    __half2 h = __floats2half2_rn(a, b);
    return *reinterpret_cast<uint32_t*>(&h);
}
__device__ __forceinline__ uint32_t ex2h2(uint32_t x) {
    uint32_t r;
    asm("ex2.approx.f16x2 %0, %1;" : "=r"(r) : "r"(x));
    return r;
}

__device__ __forceinline__ void mma16(float* c,
                                      uint32_t a0, uint32_t a1, uint32_t a2, uint32_t a3,
                                      uint32_t b0, uint32_t b1) {
    asm volatile(
        "mma.sync.aligned.m16n8k16.row.col.f32.f16.f16.f32 "
        "{%0,%1,%2,%3}, {%4,%5,%6,%7}, {%8,%9}, {%0,%1,%2,%3};"
        : "+f"(c[0]), "+f"(c[1]), "+f"(c[2]), "+f"(c[3])
        : "r"(a0), "r"(a1), "r"(a2), "r"(a3), "r"(b0), "r"(b1));
}

__device__ __forceinline__ void ldm4(uint32_t& r0, uint32_t& r1, uint32_t& r2,
                                     uint32_t& r3, uint32_t addr) {
    asm volatile("ldmatrix.sync.aligned.m8n8.x4.shared.b16 {%0,%1,%2,%3}, [%4];"
                 : "=r"(r0), "=r"(r1), "=r"(r2), "=r"(r3) : "r"(addr));
}
__device__ __forceinline__ void ldm4t(uint32_t& r0, uint32_t& r1, uint32_t& r2,
                                      uint32_t& r3, uint32_t addr) {
    asm volatile("ldmatrix.sync.aligned.m8n8.x4.trans.shared.b16 {%0,%1,%2,%3}, [%4];"
                 : "=r"(r0), "=r"(r1), "=r"(r2), "=r"(r3) : "r"(addr));
}

__device__ __forceinline__ void cpasync16(uint32_t dst, const void* src) {
    asm volatile("cp.async.cg.shared.global [%0], [%1], 16;" :: "r"(dst), "l"(src));
}
__device__ __forceinline__ void cpcommit() { asm volatile("cp.async.commit_group;"); }
__device__ __forceinline__ void cpwait0()  { asm volatile("cp.async.wait_group 0;" ::: "memory"); }

// ---------------------------------------------------------------------------
// Prepass: convert x and the four weight matrices to fp16.
// ---------------------------------------------------------------------------
__global__ void __launch_bounds__(256) round_kernel(
    const float* __restrict__ src, __half* __restrict__ dst, int n4)
{
    int i = blockIdx.x * 256 + threadIdx.x;
    if (i < n4) {
        float4 v = ((const float4*)src)[i];
        uint2 o;
        o.x = packh2(v.x, v.y);
        o.y = packh2(v.z, v.w);
        ((uint2*)dst)[i] = o;
    }
}

__global__ void __launch_bounds__(256) round_w_kernel(
    const float* __restrict__ w0, __half* __restrict__ d0,
    const float* __restrict__ w1, __half* __restrict__ d1,
    const float* __restrict__ w2, __half* __restrict__ d2,
    const float* __restrict__ w3, __half* __restrict__ d3)
{
    const float* s = w0; __half* d = d0;
    if (blockIdx.y == 1) { s = w1; d = d1; }
    else if (blockIdx.y == 2) { s = w2; d = d2; }
    else if (blockIdx.y == 3) { s = w3; d = d3; }
    int i = blockIdx.x * 256 + threadIdx.x;
    float4 v = ((const float4*)s)[i];
    uint2 o;
    o.x = packh2(v.x, v.y);
    o.y = packh2(v.z, v.w);
    ((uint2*)d)[i] = o;
}

#define GSW 36                 // word stride per 64-f16 row (144 B)

// ---------------------------------------------------------------------------
// QKV GEMM: 64x128 tiles, 3 CTAs/SM (reg-light) -> 768 tiles pack 86% into
// 444 slots (vs 65% with 128x128 on 296). C = A @ W^T + bias, fp16 out.
// 256 threads = 8 warps (2m x 4n), warp tile 32x32 (2 mt x 4 nt), k-chunk 64.
// ---------------------------------------------------------------------------
#define QGA (64 * GSW)
#define QGW (128 * GSW)
static const int QKV_SMEM = (2 * QGA + 2 * QGW) * 4;   // 55296 B

__global__ void __launch_bounds__(256, 3) gemm_qkv64(
    const __half* __restrict__ A,
    const __half* __restrict__ W0, const float* __restrict__ b0_, __half* __restrict__ C0,
    const __half* __restrict__ W1, const float* __restrict__ b1_, __half* __restrict__ C1,
    const __half* __restrict__ W2, const float* __restrict__ b2_, __half* __restrict__ C2)
{
    const int idx = blockIdx.x;
    const int z   = idx >> 8;          // 256 tiles per matrix
    const int rem = idx & 255;
    const __half* W = (z == 0) ? W0 : (z == 1) ? W1 : W2;
    const float* bias = (z == 0) ? b0_ : (z == 1) ? b1_ : b2_;
    __half* C = (z == 0) ? C0 : (z == 1) ? C1 : C2;
    const int m0 = (rem >> 2) * 64;
    const int n0 = (rem & 3) * 128;

    extern __shared__ uint32_t gsm[];  // [A0][A1][Wb0][Wb1]
    const uint32_t sbase = (uint32_t)__cvta_generic_to_shared(gsm);

    const int t    = threadIdx.x;
    const int lane = t & 31;
    const int wid  = t >> 5;
    const int g    = lane >> 2;
    const int tig  = lane & 3;
    const int wm   = (wid & 1) * 32;
    const int wn   = (wid >> 1) * 32;

    auto fill = [&](int kc, int buf) {
        uint32_t ao = sbase + buf * QGA * 4;
        uint32_t wo = sbase + (2 * QGA + buf * QGW) * 4;
#pragma unroll
        for (int i = 0; i < 2; i++) {
            int p = t + i * 256;
            int row = p >> 3, ch = p & 7;
            cpasync16(ao + (uint32_t)(row * 144 + ch * 16),
                      A + (size_t)(m0 + row) * D_ + kc + ch * 8);
        }
#pragma unroll
        for (int i = 0; i < 4; i++) {
            int p = t + i * 256;
            int row = p >> 3, ch = p & 7;
            cpasync16(wo + (uint32_t)(row * 144 + ch * 16),
                      W + (size_t)(n0 + row) * D_ + kc + ch * 8);
        }
        cpcommit();
    };

    float acc[2][4][4];
#pragma unroll
    for (int mt = 0; mt < 2; mt++)
#pragma unroll
        for (int nt = 0; nt < 4; nt++)
#pragma unroll
            for (int c = 0; c < 4; c++) acc[mt][nt][c] = 0.0f;

    fill(0, 0);

    for (int ic = 0; ic < 8; ic++) {
        cpwait0();
        __syncthreads();
        if (ic < 7) fill((ic + 1) * 64, (ic + 1) & 1);

        const uint32_t* As = gsm + (ic & 1) * QGA;
        const uint32_t* Ws = gsm + 2 * QGA + (ic & 1) * QGW;

#pragma unroll
        for (int ks = 0; ks < 4; ks++) {
            uint32_t af[2][4];
#pragma unroll
            for (int mt = 0; mt < 2; mt++) {
                int base = (wm + mt * 16 + g) * GSW + ks * 8;
                af[mt][0] = As[base + tig];
                af[mt][1] = As[base + 8 * GSW + tig];
                af[mt][2] = As[base + 4 + tig];
                af[mt][3] = As[base + 8 * GSW + 4 + tig];
            }
#pragma unroll
            for (int nt = 0; nt < 4; nt++) {
                int nb = (wn + nt * 8 + g) * GSW + ks * 8;
                uint32_t bf0 = Ws[nb + tig];
                uint32_t bf1 = Ws[nb + 4 + tig];
#pragma unroll
                for (int mt = 0; mt < 2; mt++)
                    mma16(acc[mt][nt], af[mt][0], af[mt][1], af[mt][2], af[mt][3], bf0, bf1);
            }
        }
        __syncthreads();
    }

#pragma unroll
    for (int nt = 0; nt < 4; nt++) {
        int col = n0 + wn + nt * 8 + 2 * tig;
        float2 bi = *(const float2*)(bias + col);
#pragma unroll
        for (int mt = 0; mt < 2; mt++) {
            int r = m0 + wm + mt * 16 + g;
            *(uint32_t*)(C + (size_t)r * D_ + col) =
                packh2(acc[mt][nt][0] + bi.x, acc[mt][nt][1] + bi.y);
            *(uint32_t*)(C + (size_t)(r + 8) * D_ + col) =
                packh2(acc[mt][nt][2] + bi.x, acc[mt][nt][3] + bi.y);
        }
    }
}

// ---------------------------------------------------------------------------
// Out-projection GEMM: 128x128 tiles (256 tiles = one full wave at 2 CTAs/SM).
// fp32 output.
// ---------------------------------------------------------------------------
#define GBUFW (128 * GSW)
static const int OUT_SMEM = 4 * GBUFW * 4;   // 73728 B

__global__ void __launch_bounds__(256, 2) gemm_out128(
    const __half* __restrict__ A,
    const __half* __restrict__ W, const float* __restrict__ bias,
    float* __restrict__ C)
{
    extern __shared__ uint32_t gsm[];   // [A0][A1][W0][W1]
    const uint32_t sbase = (uint32_t)__cvta_generic_to_shared(gsm);

    const int t    = threadIdx.x;
    const int lane = t & 31;
    const int wid  = t >> 5;
    const int g    = lane >> 2;
    const int tig  = lane & 3;
    const int wm   = (wid & 1) * 64;
    const int wn   = (wid >> 1) * 32;

    const int m0 = blockIdx.y * 128;
    const int n0 = blockIdx.x * 128;

    const int fr0 = t >> 3;
    const int fch = t & 7;
    const __half* Asrc = A + (size_t)(m0 + fr0) * D_ + fch * 8;
    const __half* Wsrc = W + (size_t)(n0 + fr0) * D_ + fch * 8;
    const uint32_t dB = (uint32_t)(fr0 * 144 + fch * 16);

    float acc[4][4][4];
#pragma unroll
    for (int mt = 0; mt < 4; mt++)
#pragma unroll
        for (int nt = 0; nt < 4; nt++)
#pragma unroll
            for (int c = 0; c < 4; c++) acc[mt][nt][c] = 0.0f;

    auto fill = [&](int kc, int buf) {
        uint32_t ao = sbase + buf * GBUFW * 4;
        uint32_t wo = sbase + (2 + buf) * GBUFW * 4;
#pragma unroll
        for (int i = 0; i < 4; i++) {
            uint32_t d = dB + i * 32 * 144;
            cpasync16(ao + d, Asrc + (size_t)i * 32 * D_ + kc);
            cpasync16(wo + d, Wsrc + (size_t)i * 32 * D_ + kc);
        }
        cpcommit();
    };

    fill(0, 0);

    for (int ic = 0; ic < 8; ic++) {
        cpwait0();
        __syncthreads();
        if (ic < 7) fill((ic + 1) * 64, (ic + 1) & 1);

        const uint32_t* As = gsm + (ic & 1) * GBUFW;
        const uint32_t* Ws = gsm + (2 + (ic & 1)) * GBUFW;

#pragma unroll
        for (int ks = 0; ks < 4; ks++) {
            uint32_t af[4][4];
#pragma unroll
            for (int mt = 0; mt < 4; mt++) {
                int base = (wm + mt * 16 + g) * GSW + ks * 8;
                af[mt][0] = As[base + tig];
                af[mt][1] = As[base + 8 * GSW + tig];
                af[mt][2] = As[base + 4 + tig];
                af[mt][3] = As[base + 8 * GSW + 4 + tig];
            }
#pragma unroll
            for (int nt = 0; nt < 4; nt++) {
                int nb = (wn + nt * 8 + g) * GSW + ks * 8;
                uint32_t bf0 = Ws[nb + tig];
                uint32_t bf1 = Ws[nb + 4 + tig];
#pragma unroll
                for (int mt = 0; mt < 4; mt++)
                    mma16(acc[mt][nt], af[mt][0], af[mt][1], af[mt][2], af[mt][3], bf0, bf1);
            }
        }
        __syncthreads();
    }

#pragma unroll
    for (int nt = 0; nt < 4; nt++) {
        int col = n0 + wn + nt * 8 + 2 * tig;
        float2 bi = *(const float2*)(bias + col);
#pragma unroll
        for (int mt = 0; mt < 4; mt++) {
            int r = m0 + wm + mt * 16 + g;
            *(float2*)(C + (size_t)r * D_ + col) =
                make_float2(acc[mt][nt][0] + bi.x, acc[mt][nt][1] + bi.y);
            *(float2*)(C + (size_t)(r + 8) * D_ + col) =
                make_float2(acc[mt][nt][2] + bi.x, acc[mt][nt][3] + bi.y);
        }
    }
}

// ---------------------------------------------------------------------------
// Flash attention, fp16 mma, register-resident P, f16x2 exp2. l is now
// accumulated on the (idle) fma pipe: per-thread fp32 partial sums of the
// exponentiated P pairs, one 2-hop shfl reduction at the epilogue — the
// per-tile ones-mma (6% of tensor work) is gone.
// ---------------------------------------------------------------------------
#define ASW 36
#define ABUFW (64 * ASW)

__global__ void __launch_bounds__(128, 3) attn_f16_kernel(
    const __half* __restrict__ xq, const __half* __restrict__ k,
    const __half* __restrict__ v, __half* __restrict__ out)
{
    extern __shared__ uint32_t sm[];   // [K0][K1][V0][V1]
    const uint32_t sbase = (uint32_t)__cvta_generic_to_shared(sm);

    const int t    = threadIdx.x;
    const int lane = t & 31;
    const int wid  = t >> 5;
    const int g    = lane >> 2;
    const int tig  = lane & 3;

    const int bx = gridDim.x - 1 - blockIdx.x;   // reversed schedule
    const int q0 = bx * 64;
    const int h  = blockIdx.y;
    const int b  = blockIdx.z;

    const float scale = 0.04419417382415922f * 1.44269504088896340f;  // D^-.5*log2e

    const __half* xqb = xq + (size_t)b * L_ * D_ + h * HD_;
    const __half* kb  = k  + (size_t)b * L_ * D_ + h * HD_;
    const __half* vb  = v  + (size_t)b * L_ * D_ + h * HD_;

    const int fr0 = t >> 3;
    const int fch = t & 7;
    const uint32_t dB = (uint32_t)(fr0 * 144 + fch * 16);

    auto fillKV = [&](int k0r, int buf) {
        uint32_t ko = sbase + buf * ABUFW * 4;
        uint32_t vo = sbase + (2 + buf) * ABUFW * 4;
#pragma unroll
        for (int i = 0; i < 4; i++) {
            uint32_t d = dB + i * 16 * 144;
            cpasync16(ko + d, kb + (size_t)(k0r + fr0 + i * 16) * D_ + fch * 8);
            cpasync16(vo + d, vb + (size_t)(k0r + fr0 + i * 16) * D_ + fch * 8);
        }
        cpcommit();
    };

    fillKV(0, 0);   // tile 0

    // ---- Q staging into Kbuf1: fused upsample + scale + f16 pack ----
    uint32_t* Qw = sm + ABUFW;
#pragma unroll
    for (int i = 0; i < 8; i++) {
        int f    = i * 128 + t;
        int row  = f >> 4;            // 0..63
        int c4   = (f & 15) * 4;      // dim base
        int qrow = q0 + row;
        float4 val;
        if (qrow == 0) {
            __half2 p0 = *(const __half2*)(xqb + c4);
            __half2 p1 = *(const __half2*)(xqb + c4 + 2);
            float2 f0 = __half22float2(p0), f1 = __half22float2(p1);
            val = make_float4(f0.x, f0.y, f1.x, f1.y);
        } else {
            float src = (qrow - 0.5f) * 0.5f;
            int i0 = (int)src;
            float w = src - (float)i0;
            int i1 = min(i0 + 1, L_ - 1);
            __half2 a0 = *(const __half2*)(xqb + (size_t)i0 * D_ + c4);
            __half2 a1 = *(const __half2*)(xqb + (size_t)i0 * D_ + c4 + 2);
            __half2 c0 = *(const __half2*)(xqb + (size_t)i1 * D_ + c4);
            __half2 c1 = *(const __half2*)(xqb + (size_t)i1 * D_ + c4 + 2);
            float2 fa0 = __half22float2(a0), fa1 = __half22float2(a1);
            float2 fc0 = __half22float2(c0), fc1 = __half22float2(c1);
            val.x = fa0.x + (fc0.x - fa0.x) * w;
            val.y = fa0.y + (fc0.y - fa0.y) * w;
            val.z = fa1.x + (fc1.x - fa1.x) * w;
            val.w = fa1.y + (fc1.y - fa1.y) * w;
        }
        uint2 o;
        o.x = packh2(val.x * scale, val.y * scale);
        o.y = packh2(val.z * scale, val.w * scale);
        *(uint2*)&Qw[row * ASW + c4 / 2] = o;
    }
    __syncthreads();

    // ---- Q A-fragments to registers (Kbuf1 free afterwards) ----
    uint32_t qf[4][4];
    {
        int r0 = (wid * 16 + g) * ASW;
        int r1 = (wid * 16 + g + 8) * ASW;
#pragma unroll
        for (int ks = 0; ks < 4; ks++) {
            qf[ks][0] = Qw[r0 + ks * 8 + tig];
            qf[ks][1] = Qw[r1 + ks * 8 + tig];
            qf[ks][2] = Qw[r0 + ks * 8 + 4 + tig];
            qf[ks][3] = Qw[r1 + ks * 8 + 4 + tig];
        }
    }

    float oacc[8][4];
#pragma unroll
    for (int nt = 0; nt < 8; nt++)
#pragma unroll
        for (int c = 0; c < 4; c++) oacc[nt][c] = 0.0f;
    float lsum0 = 0.0f, lsum1 = 0.0f;   // fp32 row-sum partials (rows g / g+8)

    const int ntiles = min(bx + 1, L_ / 64);
    const int qrow_w = q0 + wid * 16;

    // ldmatrix per-lane offsets
    const int krow = ((lane >> 4) & 1) * 8 + (lane & 7);   // K (non-trans)
    const int kdim = ((lane >> 3) & 1) * 8;
    const int vrow = ((lane >> 3) & 1) * 8 + (lane & 7);   // V (.trans)
    const int vdim = ((lane >> 4) & 1) * 8;

    for (int tile = 0; tile < ntiles; tile++) {
        const int k0 = tile * 64;
        cpwait0();
        __syncthreads();   // tile data visible; all warps done with prev KV reads

        if (tile + 1 < ntiles) fillKV(k0 + 64, (tile + 1) & 1);

        const uint32_t kbyte = sbase + (tile & 1) * ABUFW * 4;
        const uint32_t vbyte = sbase + (2 + (tile & 1)) * ABUFW * 4;

        // ---- S = Q @ K^T ----
        float sacc[8][4];
#pragma unroll
        for (int nt = 0; nt < 8; nt++)
#pragma unroll
            for (int c = 0; c < 4; c++) sacc[nt][c] = 0.0f;

#pragma unroll
        for (int ks = 0; ks < 4; ks++) {
#pragma unroll
            for (int ngp = 0; ngp < 4; ngp++) {
                uint32_t r0, r1, r2, r3;
                ldm4(r0, r1, r2, r3,
                     kbyte + (ngp * 16 + krow) * 144 + (ks * 16 + kdim) * 2);
                mma16(sacc[2 * ngp],     qf[ks][0], qf[ks][1], qf[ks][2], qf[ks][3], r0, r1);
                mma16(sacc[2 * ngp + 1], qf[ks][0], qf[ks][1], qf[ks][2], qf[ks][3], r2, r3);
            }
        }

        // ---- causal mask (diagonal tile only) ----
        if (k0 == q0) {
            int r0 = qrow_w + g;
            int r1 = r0 + 8;
#pragma unroll
            for (int nt = 0; nt < 8; nt++) {
                int col = k0 + nt * 8 + 2 * tig;
                if (col     > r0) sacc[nt][0] = -1e30f;
                if (col + 1 > r0) sacc[nt][1] = -1e30f;
                if (col     > r1) sacc[nt][2] = -1e30f;
                if (col + 1 > r1) sacc[nt][3] = -1e30f;
            }
        }

        // ---- pack + exp2 (f16x2); accumulate l on the fma pipe in fp32 ----
        uint32_t ph[8][2];
#pragma unroll
        for (int nt = 0; nt < 8; nt++) {
            ph[nt][0] = ex2h2(packh2(sacc[nt][0], sacc[nt][1]));
            ph[nt][1] = ex2h2(packh2(sacc[nt][2], sacc[nt][3]));
            float2 e0 = __half22float2(*reinterpret_cast<__half2*>(&ph[nt][0]));
            float2 e1 = __half22float2(*reinterpret_cast<__half2*>(&ph[nt][1]));
            lsum0 += e0.x + e0.y;
            lsum1 += e1.x + e1.y;
        }

        // ---- O += P @ V with register P ----
#pragma unroll
        for (int ks = 0; ks < 4; ks++) {
            uint32_t pa0 = ph[2 * ks][0];
            uint32_t pa1 = ph[2 * ks][1];
            uint32_t pa2 = ph[2 * ks + 1][0];
            uint32_t pa3 = ph[2 * ks + 1][1];
#pragma unroll
            for (int ngp = 0; ngp < 4; ngp++) {
                uint32_t r0v, r1v, r2v, r3v;
                ldm4t(r0v, r1v, r2v, r3v,
                      vbyte + (ks * 16 + vrow) * 144 + (ngp * 16 + vdim) * 2);
                mma16(oacc[2 * ngp],     pa0, pa1, pa2, pa3, r0v, r1v);
                mma16(oacc[2 * ngp + 1], pa0, pa1, pa2, pa3, r2v, r3v);
            }
        }
    }

    // ---- epilogue: finish l (2-hop shfl over the 4-lane row group) ----
    lsum0 += __shfl_xor_sync(0xffffffffu, lsum0, 1);
    lsum0 += __shfl_xor_sync(0xffffffffu, lsum0, 2);
    lsum1 += __shfl_xor_sync(0xffffffffu, lsum1, 1);
    lsum1 += __shfl_xor_sync(0xffffffffu, lsum1, 2);
    float inv0 = 1.0f / lsum0;
    float inv1 = 1.0f / lsum1;
    __half* ob = out + ((size_t)b * Q_ + qrow_w) * D_ + h * HD_;
#pragma unroll
    for (int nt = 0; nt < 8; nt++) {
        int col = nt * 8 + 2 * tig;
        *(uint32_t*)(ob + (size_t)g * D_ + col) =
            packh2(oacc[nt][0] * inv0, oacc[nt][1] * inv0);
        *(uint32_t*)(ob + (size_t)(g + 8) * D_ + col) =
            packh2(oacc[nt][2] * inv1, oacc[nt][3] * inv1);
    }
}

// ---------------------------------------------------------------------------
// Launch
// ---------------------------------------------------------------------------
static const int ATT_SMEM = 4 * ABUFW * 4;   // 36864 B

extern "C" void kernel_launch(void* const* d_in, const int* in_sizes, int n_in,
                              void* d_out, int out_size)
{
    const float* x  = (const float*)d_in[0];
    const float* Wq = (const float*)d_in[1];
    const float* bq = (const float*)d_in[2];
    const float* Wk = (const float*)d_in[3];
    const float* bk = (const float*)d_in[4];
    const float* Wv = (const float*)d_in[5];
    const float* bv = (const float*)d_in[6];
    const float* Wo = (const float*)d_in[7];
    const float* bo = (const float*)d_in[8];
    float* out = (float*)d_out;

    __half *rx, *rwq, *rwk, *rwv, *rwo, *xq, *kk, *vv, *ao;
    cudaGetSymbolAddress((void**)&rx,  g_x);
    cudaGetSymbolAddress((void**)&rwq, g_wq);
    cudaGetSymbolAddress((void**)&rwk, g_wk);
    cudaGetSymbolAddress((void**)&rwv, g_wv);
    cudaGetSymbolAddress((void**)&rwo, g_wo);
    cudaGetSymbolAddress((void**)&xq,  g_xq);
    cudaGetSymbolAddress((void**)&kk,  g_k);
    cudaGetSymbolAddress((void**)&vv,  g_v);
    cudaGetSymbolAddress((void**)&ao,  g_ao);

    cudaFuncSetAttribute(gemm_qkv64,
                         cudaFuncAttributeMaxDynamicSharedMemorySize, QKV_SMEM);
    cudaFuncSetAttribute(gemm_out128,
                         cudaFuncAttributeMaxDynamicSharedMemorySize, OUT_SMEM);
    cudaFuncSetAttribute(attn_f16_kernel,
                         cudaFuncAttributeMaxDynamicSharedMemorySize, ATT_SMEM);

    // Prepass: f32 -> f16
    round_kernel<<<(B_ * L_ * D_ / 4 + 255) / 256, 256>>>(x, rx, B_ * L_ * D_ / 4);
    round_w_kernel<<<dim3(D_ * D_ / 4 / 256, 4), 256>>>(Wq, rwq, Wk, rwk, Wv, rwv, Wo, rwo);

    // Fused QKV projections: 768 tiles of 64x128 at 3 CTAs/SM
    gemm_qkv64<<<768, 256, QKV_SMEM>>>(rx,
                                       rwq, bq, xq,
                                       rwk, bk, kk,
                                       rwv, bv, vv);

    // Flash attention
    attn_f16_kernel<<<dim3(Q_ / 64, H_, B_), 128, ATT_SMEM>>>(xq, kk, vv, ao);

    // Output projection: 256 tiles of 128x128 (single wave), fp32 out
    gemm_out128<<<dim3(D_ / 128, (B_ * Q_) / 128), 256, OUT_SMEM>>>(ao, rwo, bo, out);
}

// round 16
// speedup vs baseline: 1.0260x; 1.0260x over previous
#include <cuda_runtime.h>
#include <cuda_fp16.h>
#include <cstdint>

// Problem constants
#define B_   2
#define L_   2048
#define Q_   4096
#define D_   512
#define H_   8
#define HD_  64

// ---------------------------------------------------------------------------
// Scratch (allocation-free __device__ globals), all fp16.
// ---------------------------------------------------------------------------
__device__ __half g_x [B_ * L_ * D_];
__device__ __half g_wq[D_ * D_];
__device__ __half g_wk[D_ * D_];
__device__ __half g_wv[D_ * D_];
__device__ __half g_wo[D_ * D_];
__device__ __half g_xq[B_ * L_ * D_];
__device__ __half g_k [B_ * L_ * D_];
__device__ __half g_v [B_ * L_ * D_];
__device__ __half g_ao[B_ * Q_ * D_];

// ---------------------------------------------------------------------------
// Helpers
// ---------------------------------------------------------------------------
__device__ __forceinline__ uint32_t packh2(float a, float b) {
    __half2 h = __floats2half2_rn(a, b);
    return *reinterpret_cast<uint32_t*>(&h);
}
__device__ __forceinline__ uint32_t ex2h2(uint32_t x) {
    uint32_t r;
    asm("ex2.approx.f16x2 %0, %1;" : "=r"(r) : "r"(x));
    return r;
}

__device__ __forceinline__ void mma16(float* c,
                                      uint32_t a0, uint32_t a1, uint32_t a2, uint32_t a3,
                                      uint32_t b0, uint32_t b1) {
    asm volatile(
        "mma.sync.aligned.m16n8k16.row.col.f32.f16.f16.f32 "
        "{%0,%1,%2,%3}, {%4,%5,%6,%7}, {%8,%9}, {%0,%1,%2,%3};"
        : "+f"(c[0]), "+f"(c[1]), "+f"(c[2]), "+f"(c[3])
        : "r"(a0), "r"(a1), "r"(a2), "r"(a3), "r"(b0), "r"(b1));
}

__device__ __forceinline__ void ldm4(uint32_t& r0, uint32_t& r1, uint32_t& r2,
                                     uint32_t& r3, uint32_t addr) {
    asm volatile("ldmatrix.sync.aligned.m8n8.x4.shared.b16 {%0,%1,%2,%3}, [%4];"
                 : "=r"(r0), "=r"(r1), "=r"(r2), "=r"(r3) : "r"(addr));
}
__device__ __forceinline__ void ldm4t(uint32_t& r0, uint32_t& r1, uint32_t& r2,
                                      uint32_t& r3, uint32_t addr) {
    asm volatile("ldmatrix.sync.aligned.m8n8.x4.trans.shared.b16 {%0,%1,%2,%3}, [%4];"
                 : "=r"(r0), "=r"(r1), "=r"(r2), "=r"(r3) : "r"(addr));
}

__device__ __forceinline__ void cpasync16(uint32_t dst, const void* src) {
    asm volatile("cp.async.cg.shared.global [%0], [%1], 16;" :: "r"(dst), "l"(src));
}
__device__ __forceinline__ void cpcommit() { asm volatile("cp.async.commit_group;"); }
__device__ __forceinline__ void cpwait0()  { asm volatile("cp.async.wait_group 0;" ::: "memory"); }

// ---------------------------------------------------------------------------
// Prepass: convert x and the four weight matrices to fp16.
// ---------------------------------------------------------------------------
__global__ void __launch_bounds__(256) round_kernel(
    const float* __restrict__ src, __half* __restrict__ dst, int n4)
{
    int i = blockIdx.x * 256 + threadIdx.x;
    if (i < n4) {
        float4 v = ((const float4*)src)[i];
        uint2 o;
        o.x = packh2(v.x, v.y);
        o.y = packh2(v.z, v.w);
        ((uint2*)dst)[i] = o;
    }
}

__global__ void __launch_bounds__(256) round_w_kernel(
    const float* __restrict__ w0, __half* __restrict__ d0,
    const float* __restrict__ w1, __half* __restrict__ d1,
    const float* __restrict__ w2, __half* __restrict__ d2,
    const float* __restrict__ w3, __half* __restrict__ d3)
{
    const float* s = w0; __half* d = d0;
    if (blockIdx.y == 1) { s = w1; d = d1; }
    else if (blockIdx.y == 2) { s = w2; d = d2; }
    else if (blockIdx.y == 3) { s = w3; d = d3; }
    int i = blockIdx.x * 256 + threadIdx.x;
    float4 v = ((const float4*)s)[i];
    uint2 o;
    o.x = packh2(v.x, v.y);
    o.y = packh2(v.z, v.w);
    ((uint2*)d)[i] = o;
}

// ---------------------------------------------------------------------------
// fp16 GEMM (R14 config — measured best): 128x128 tiles, k-chunk 64, 256
// threads = 8 warps (2m x 4n), warp tile 64x32. grid.z picks (W,bias,C).
// ---------------------------------------------------------------------------
#define GSW 36                 // word stride per 64-f16 row (144 B)
#define GBUFW (128 * GSW)

__global__ void __launch_bounds__(256, 2) gemm_f16(
    const __half* __restrict__ A,
    const __half* __restrict__ W0, const float* __restrict__ b0_, void* __restrict__ C0,
    const __half* __restrict__ W1, const float* __restrict__ b1_, void* __restrict__ C1,
    const __half* __restrict__ W2, const float* __restrict__ b2_, void* __restrict__ C2,
    int roundOut)
{
    const __half* W = W0; const float* bias = b0_; void* C = C0;
    if (blockIdx.z == 1) { W = W1; bias = b1_; C = C1; }
    else if (blockIdx.z == 2) { W = W2; bias = b2_; C = C2; }

    extern __shared__ uint32_t gsm[];   // [A0][A1][W0][W1]
    const uint32_t sbase = (uint32_t)__cvta_generic_to_shared(gsm);

    const int t    = threadIdx.x;
    const int lane = t & 31;
    const int wid  = t >> 5;
    const int g    = lane >> 2;
    const int tig  = lane & 3;
    const int wm   = (wid & 1) * 64;
    const int wn   = (wid >> 1) * 32;

    const int m0 = blockIdx.y * 128;
    const int n0 = blockIdx.x * 128;

    const int fr0 = t >> 3;
    const int fch = t & 7;
    const __half* Asrc = A + (size_t)(m0 + fr0) * D_ + fch * 8;
    const __half* Wsrc = W + (size_t)(n0 + fr0) * D_ + fch * 8;
    const uint32_t dB = (uint32_t)(fr0 * 144 + fch * 16);

    float acc[4][4][4];
#pragma unroll
    for (int mt = 0; mt < 4; mt++)
#pragma unroll
        for (int nt = 0; nt < 4; nt++)
#pragma unroll
            for (int c = 0; c < 4; c++) acc[mt][nt][c] = 0.0f;

    auto fill = [&](int kc, int buf) {
        uint32_t ao = sbase + buf * GBUFW * 4;
        uint32_t wo = sbase + (2 + buf) * GBUFW * 4;
#pragma unroll
        for (int i = 0; i < 4; i++) {
            uint32_t d = dB + i * 32 * 144;
            cpasync16(ao + d, Asrc + (size_t)i * 32 * D_ + kc);
            cpasync16(wo + d, Wsrc + (size_t)i * 32 * D_ + kc);
        }
        cpcommit();
    };

    fill(0, 0);

    for (int ic = 0; ic < 8; ic++) {
        cpwait0();
        __syncthreads();
        if (ic < 7) fill((ic + 1) * 64, (ic + 1) & 1);

        const uint32_t* As = gsm + (ic & 1) * GBUFW;
        const uint32_t* Ws = gsm + (2 + (ic & 1)) * GBUFW;

#pragma unroll
        for (int ks = 0; ks < 4; ks++) {
            uint32_t af[4][4];
#pragma unroll
            for (int mt = 0; mt < 4; mt++) {
                int base = (wm + mt * 16 + g) * GSW + ks * 8;
                af[mt][0] = As[base + tig];
                af[mt][1] = As[base + 8 * GSW + tig];
                af[mt][2] = As[base + 4 + tig];
                af[mt][3] = As[base + 8 * GSW + 4 + tig];
            }
#pragma unroll
            for (int nt = 0; nt < 4; nt++) {
                int nb = (wn + nt * 8 + g) * GSW + ks * 8;
                uint32_t bf0 = Ws[nb + tig];
                uint32_t bf1 = Ws[nb + 4 + tig];
#pragma unroll
                for (int mt = 0; mt < 4; mt++)
                    mma16(acc[mt][nt], af[mt][0], af[mt][1], af[mt][2], af[mt][3], bf0, bf1);
            }
        }
        __syncthreads();   // fragment reads done before this buffer is refilled
    }

    // Epilogue
#pragma unroll
    for (int nt = 0; nt < 4; nt++) {
        int col = n0 + wn + nt * 8 + 2 * tig;
        float2 bi = *(const float2*)(bias + col);
#pragma unroll
        for (int mt = 0; mt < 4; mt++) {
            int r = m0 + wm + mt * 16 + g;
            float x0 = acc[mt][nt][0] + bi.x, y0 = acc[mt][nt][1] + bi.y;
            float x1 = acc[mt][nt][2] + bi.x, y1 = acc[mt][nt][3] + bi.y;
            if (roundOut) {
                __half* Ch = (__half*)C;
                *(uint32_t*)(Ch + (size_t)r * D_ + col)       = packh2(x0, y0);
                *(uint32_t*)(Ch + (size_t)(r + 8) * D_ + col) = packh2(x1, y1);
            } else {
                float* Cf = (float*)C;
                *(float2*)(Cf + (size_t)r * D_ + col)       = make_float2(x0, y0);
                *(float2*)(Cf + (size_t)(r + 8) * D_ + col) = make_float2(x1, y1);
            }
        }
    }
}

// ---------------------------------------------------------------------------
// Flash attention (R15 config — measured best, 103.1 us): fp16 mma, register-
// resident P, f16x2 exp2, l accumulated on the fma pipe (no ones-mma).
// ---------------------------------------------------------------------------
#define ASW 36
#define ABUFW (64 * ASW)

__global__ void __launch_bounds__(128, 3) attn_f16_kernel(
    const __half* __restrict__ xq, const __half* __restrict__ k,
    const __half* __restrict__ v, __half* __restrict__ out)
{
    extern __shared__ uint32_t sm[];   // [K0][K1][V0][V1]
    const uint32_t sbase = (uint32_t)__cvta_generic_to_shared(sm);

    const int t    = threadIdx.x;
    const int lane = t & 31;
    const int wid  = t >> 5;
    const int g    = lane >> 2;
    const int tig  = lane & 3;

    const int bx = gridDim.x - 1 - blockIdx.x;   // reversed schedule
    const int q0 = bx * 64;
    const int h  = blockIdx.y;
    const int b  = blockIdx.z;

    const float scale = 0.04419417382415922f * 1.44269504088896340f;  // D^-.5*log2e

    const __half* xqb = xq + (size_t)b * L_ * D_ + h * HD_;
    const __half* kb  = k  + (size_t)b * L_ * D_ + h * HD_;
    const __half* vb  = v  + (size_t)b * L_ * D_ + h * HD_;

    const int fr0 = t >> 3;
    const int fch = t & 7;
    const uint32_t dB = (uint32_t)(fr0 * 144 + fch * 16);

    auto fillKV = [&](int k0r, int buf) {
        uint32_t ko = sbase + buf * ABUFW * 4;
        uint32_t vo = sbase + (2 + buf) * ABUFW * 4;
#pragma unroll
        for (int i = 0; i < 4; i++) {
            uint32_t d = dB + i * 16 * 144;
            cpasync16(ko + d, kb + (size_t)(k0r + fr0 + i * 16) * D_ + fch * 8);
            cpasync16(vo + d, vb + (size_t)(k0r + fr0 + i * 16) * D_ + fch * 8);
        }
        cpcommit();
    };

    fillKV(0, 0);   // tile 0

    // ---- Q staging into Kbuf1: fused upsample + scale + f16 pack ----
    uint32_t* Qw = sm + ABUFW;
#pragma unroll
    for (int i = 0; i < 8; i++) {
        int f    = i * 128 + t;
        int row  = f >> 4;            // 0..63
        int c4   = (f & 15) * 4;      // dim base
        int qrow = q0 + row;
        float4 val;
        if (qrow == 0) {
            __half2 p0 = *(const __half2*)(xqb + c4);
            __half2 p1 = *(const __half2*)(xqb + c4 + 2);
            float2 f0 = __half22float2(p0), f1 = __half22float2(p1);
            val = make_float4(f0.x, f0.y, f1.x, f1.y);
        } else {
            float src = (qrow - 0.5f) * 0.5f;
            int i0 = (int)src;
            float w = src - (float)i0;
            int i1 = min(i0 + 1, L_ - 1);
            __half2 a0 = *(const __half2*)(xqb + (size_t)i0 * D_ + c4);
            __half2 a1 = *(const __half2*)(xqb + (size_t)i0 * D_ + c4 + 2);
            __half2 c0 = *(const __half2*)(xqb + (size_t)i1 * D_ + c4);
            __half2 c1 = *(const __half2*)(xqb + (size_t)i1 * D_ + c4 + 2);
            float2 fa0 = __half22float2(a0), fa1 = __half22float2(a1);
            float2 fc0 = __half22float2(c0), fc1 = __half22float2(c1);
            val.x = fa0.x + (fc0.x - fa0.x) * w;
            val.y = fa0.y + (fc0.y - fa0.y) * w;
            val.z = fa1.x + (fc1.x - fa1.x) * w;
            val.w = fa1.y + (fc1.y - fa1.y) * w;
        }
        uint2 o;
        o.x = packh2(val.x * scale, val.y * scale);
        o.y = packh2(val.z * scale, val.w * scale);
        *(uint2*)&Qw[row * ASW + c4 / 2] = o;
    }
    __syncthreads();

    // ---- Q A-fragments to registers (Kbuf1 free afterwards) ----
    uint32_t qf[4][4];
    {
        int r0 = (wid * 16 + g) * ASW;
        int r1 = (wid * 16 + g + 8) * ASW;
#pragma unroll
        for (int ks = 0; ks < 4; ks++) {
            qf[ks][0] = Qw[r0 + ks * 8 + tig];
            qf[ks][1] = Qw[r1 + ks * 8 + tig];
            qf[ks][2] = Qw[r0 + ks * 8 + 4 + tig];
            qf[ks][3] = Qw[r1 + ks * 8 + 4 + tig];
        }
    }

    float oacc[8][4];
#pragma unroll
    for (int nt = 0; nt < 8; nt++)
#pragma unroll
        for (int c = 0; c < 4; c++) oacc[nt][c] = 0.0f;
    float lsum0 = 0.0f, lsum1 = 0.0f;   // fp32 row-sum partials (rows g / g+8)

    const int ntiles = min(bx + 1, L_ / 64);
    const int qrow_w = q0 + wid * 16;

    // ldmatrix per-lane offsets
    const int krow = ((lane >> 4) & 1) * 8 + (lane & 7);   // K (non-trans)
    const int kdim = ((lane >> 3) & 1) * 8;
    const int vrow = ((lane >> 3) & 1) * 8 + (lane & 7);   // V (.trans)
    const int vdim = ((lane >> 4) & 1) * 8;

    for (int tile = 0; tile < ntiles; tile++) {
        const int k0 = tile * 64;
        cpwait0();
        __syncthreads();   // tile data visible; all warps done with prev KV reads

        if (tile + 1 < ntiles) fillKV(k0 + 64, (tile + 1) & 1);

        const uint32_t kbyte = sbase + (tile & 1) * ABUFW * 4;
        const uint32_t vbyte = sbase + (2 + (tile & 1)) * ABUFW * 4;

        // ---- S = Q @ K^T ----
        float sacc[8][4];
#pragma unroll
        for (int nt = 0; nt < 8; nt++)
#pragma unroll
            for (int c = 0; c < 4; c++) sacc[nt][c] = 0.0f;

#pragma unroll
        for (int ks = 0; ks < 4; ks++) {
#pragma unroll
            for (int ngp = 0; ngp < 4; ngp++) {
                uint32_t r0, r1, r2, r3;
                ldm4(r0, r1, r2, r3,
                     kbyte + (ngp * 16 + krow) * 144 + (ks * 16 + kdim) * 2);
                mma16(sacc[2 * ngp],     qf[ks][0], qf[ks][1], qf[ks][2], qf[ks][3], r0, r1);
                mma16(sacc[2 * ngp + 1], qf[ks][0], qf[ks][1], qf[ks][2], qf[ks][3], r2, r3);
            }
        }

        // ---- causal mask (diagonal tile only) ----
        if (k0 == q0) {
            int r0 = qrow_w + g;
            int r1 = r0 + 8;
#pragma unroll
            for (int nt = 0; nt < 8; nt++) {
                int col = k0 + nt * 8 + 2 * tig;
                if (col     > r0) sacc[nt][0] = -1e30f;
                if (col + 1 > r0) sacc[nt][1] = -1e30f;
                if (col     > r1) sacc[nt][2] = -1e30f;
                if (col + 1 > r1) sacc[nt][3] = -1e30f;
            }
        }

        // ---- pack + exp2 (f16x2); accumulate l on the fma pipe in fp32 ----
        uint32_t ph[8][2];
#pragma unroll
        for (int nt = 0; nt < 8; nt++) {
            ph[nt][0] = ex2h2(packh2(sacc[nt][0], sacc[nt][1]));
            ph[nt][1] = ex2h2(packh2(sacc[nt][2], sacc[nt][3]));
            float2 e0 = __half22float2(*reinterpret_cast<__half2*>(&ph[nt][0]));
            float2 e1 = __half22float2(*reinterpret_cast<__half2*>(&ph[nt][1]));
            lsum0 += e0.x + e0.y;
            lsum1 += e1.x + e1.y;
        }

        // ---- O += P @ V with register P ----
#pragma unroll
        for (int ks = 0; ks < 4; ks++) {
            uint32_t pa0 = ph[2 * ks][0];
            uint32_t pa1 = ph[2 * ks][1];
            uint32_t pa2 = ph[2 * ks + 1][0];
            uint32_t pa3 = ph[2 * ks + 1][1];
#pragma unroll
            for (int ngp = 0; ngp < 4; ngp++) {
                uint32_t r0v, r1v, r2v, r3v;
                ldm4t(r0v, r1v, r2v, r3v,
                      vbyte + (ks * 16 + vrow) * 144 + (ngp * 16 + vdim) * 2);
                mma16(oacc[2 * ngp],     pa0, pa1, pa2, pa3, r0v, r1v);
                mma16(oacc[2 * ngp + 1], pa0, pa1, pa2, pa3, r2v, r3v);
            }
        }
    }

    // ---- epilogue: finish l (2-hop shfl over the 4-lane row group) ----
    lsum0 += __shfl_xor_sync(0xffffffffu, lsum0, 1);
    lsum0 += __shfl_xor_sync(0xffffffffu, lsum0, 2);
    lsum1 += __shfl_xor_sync(0xffffffffu, lsum1, 1);
    lsum1 += __shfl_xor_sync(0xffffffffu, lsum1, 2);
    float inv0 = 1.0f / lsum0;
    float inv1 = 1.0f / lsum1;
    __half* ob = out + ((size_t)b * Q_ + qrow_w) * D_ + h * HD_;
#pragma unroll
    for (int nt = 0; nt < 8; nt++) {
        int col = nt * 8 + 2 * tig;
        *(uint32_t*)(ob + (size_t)g * D_ + col) =
            packh2(oacc[nt][0] * inv0, oacc[nt][1] * inv0);
        *(uint32_t*)(ob + (size_t)(g + 8) * D_ + col) =
            packh2(oacc[nt][2] * inv1, oacc[nt][3] * inv1);
    }
}

// ---------------------------------------------------------------------------
// Launch
// ---------------------------------------------------------------------------
static const int GEMM_SMEM = 4 * GBUFW * 4;   // 73728 B
static const int ATT_SMEM  = 4 * ABUFW * 4;   // 36864 B

extern "C" void kernel_launch(void* const* d_in, const int* in_sizes, int n_in,
                              void* d_out, int out_size)
{
    const float* x  = (const float*)d_in[0];
    const float* Wq = (const float*)d_in[1];
    const float* bq = (const float*)d_in[2];
    const float* Wk = (const float*)d_in[3];
    const float* bk = (const float*)d_in[4];
    const float* Wv = (const float*)d_in[5];
    const float* bv = (const float*)d_in[6];
    const float* Wo = (const float*)d_in[7];
    const float* bo = (const float*)d_in[8];
    float* out = (float*)d_out;

    __half *rx, *rwq, *rwk, *rwv, *rwo, *xq, *kk, *vv, *ao;
    cudaGetSymbolAddress((void**)&rx,  g_x);
    cudaGetSymbolAddress((void**)&rwq, g_wq);
    cudaGetSymbolAddress((void**)&rwk, g_wk);
    cudaGetSymbolAddress((void**)&rwv, g_wv);
    cudaGetSymbolAddress((void**)&rwo, g_wo);
    cudaGetSymbolAddress((void**)&xq,  g_xq);
    cudaGetSymbolAddress((void**)&kk,  g_k);
    cudaGetSymbolAddress((void**)&vv,  g_v);
    cudaGetSymbolAddress((void**)&ao,  g_ao);

    cudaFuncSetAttribute(gemm_f16,
                         cudaFuncAttributeMaxDynamicSharedMemorySize, GEMM_SMEM);
    cudaFuncSetAttribute(attn_f16_kernel,
                         cudaFuncAttributeMaxDynamicSharedMemorySize, ATT_SMEM);

    // Prepass: f32 -> f16
    round_kernel<<<(B_ * L_ * D_ / 4 + 255) / 256, 256>>>(x, rx, B_ * L_ * D_ / 4);
    round_w_kernel<<<dim3(D_ * D_ / 4 / 256, 4), 256>>>(Wq, rwq, Wk, rwk, Wv, rwv, Wo, rwo);

    // Fused QKV projections (fp16 outputs)
    dim3 gqkv(D_ / 128, (B_ * L_) / 128, 3);
    gemm_f16<<<gqkv, 256, GEMM_SMEM>>>(rx,
                                       rwq, bq, xq,
                                       rwk, bk, kk,
                                       rwv, bv, vv, 1);

    // Flash attention (fp16 mma, register P, l on fma pipe)
    attn_f16_kernel<<<dim3(Q_ / 64, H_, B_), 128, ATT_SMEM>>>(xq, kk, vv, ao);

    // Output projection (fp32 output)
    dim3 gout(D_ / 128, (B_ * Q_) / 128, 1);
    gemm_f16<<<gout, 256, GEMM_SMEM>>>(ao,
                                       rwo, bo, out,
                                       rwo, bo, out,
                                       rwo, bo, out, 0);
}